// round 5
// baseline (speedup 1.0000x reference)
#include <cuda_runtime.h>
#include <cuda_bf16.h>

// SymmetryLoss: chamfer(mirror(xyz), xyz), yz-plane mirror.
// xyz: (B=16, 3, N=4096) fp32 NCHW -> scalar loss.
//
// d2 matrix is symmetric (mirror is an involutive isometry):
//   loss = (2/(B*N)) * sum_{b,n} min_m [ a2_n + (b2_m - 2 a_n.b_m) ]
// Inner loop vectorized over m with fma.rn.f32x2 (FFMA2, sm_103a):
//   3 FFMA2 + 2 FMNMX per (1 n-point x 2 m-points).

#define BATCH   16
#define NPTS    4096
#define THREADS 256
#define UPT     2                 // n-points per thread
#define CHUNK   (THREADS * UPT)   // 512
#define NCHUNK  (NPTS / CHUNK)    // 8
#define GRID    (BATCH * NCHUNK)  // 128
#define MTILE   2048              // m-points per smem tile
#define PAIRS   (MTILE / 2)       // 1024 m-pairs

__device__ float g_partials[GRID];
__device__ int   g_count = 0;

// (lo,hi) = ax*xx + ay*yy + az*zz + ww, elementwise on f32x2 lanes.
__device__ __forceinline__ void dot2(
    unsigned long long axd, unsigned long long ayd, unsigned long long azd,
    unsigned long long xx, unsigned long long yy,
    unsigned long long zz, unsigned long long ww,
    float& lo, float& hi)
{
    asm("{\n\t"
        ".reg .b64 t;\n\t"
        "fma.rn.f32x2 t, %4, %7, %8;\n\t"   // az*zz + ww
        "fma.rn.f32x2 t, %3, %6, t;\n\t"    // + ay*yy
        "fma.rn.f32x2 t, %2, %5, t;\n\t"    // + ax*xx
        "mov.b64 {%0, %1}, t;\n\t"
        "}"
        : "=f"(lo), "=f"(hi)
        : "l"(axd), "l"(ayd), "l"(azd), "l"(xx), "l"(yy), "l"(zz), "l"(ww));
}

__device__ __forceinline__ unsigned long long dupf(float v)
{
    unsigned long long d;
    asm("mov.b64 %0, {%1, %1};" : "=l"(d) : "f"(v));
    return d;
}

__global__ __launch_bounds__(THREADS)
void chamfer_sym_kernel(const float* __restrict__ xyz, float* __restrict__ out)
{
    // Pair p occupies sm2[2p] = (xx, yy), sm2[2p+1] = (zz, ww); each .x/.y is f32x2.
    __shared__ ulonglong2 sm2[2 * PAIRS];          // 32 KB
    __shared__ float      red[THREADS / 32];
    __shared__ bool       is_last;

    const int blk = blockIdx.x;
    const int b   = blk >> 3;            // / NCHUNK
    const int c   = blk & (NCHUNK - 1);
    const int t   = threadIdx.x;

    const float* __restrict__ px = xyz + (size_t)b * 3 * NPTS;
    const float* __restrict__ py = px + NPTS;
    const float* __restrict__ pz = px + 2 * NPTS;

    // Mirrored a-points, duplicated into f32x2 lanes.
    unsigned long long axd[UPT], ayd[UPT], azd[UPT];
    float a2[UPT], eml[UPT], emh[UPT];
#pragma unroll
    for (int u = 0; u < UPT; u++) {
        const int n = c * CHUNK + u * THREADS + t;
        const float x = px[n], y = py[n], z = pz[n];
        axd[u] = dupf(-x);
        ayd[u] = dupf(y);
        azd[u] = dupf(z);
        a2[u]  = x * x + y * y + z * z;
        eml[u] = 3.4e38f;
        emh[u] = 3.4e38f;
    }

    float* smf = (float*)sm2;
    for (int tile = 0; tile < NPTS; tile += MTILE) {
        __syncthreads();
        // Fill interleaved pair tile: floats at 8p + {0,1:xx, 2,3:yy, 4,5:zz, 6,7:ww}
        for (int j = t; j < MTILE; j += THREADS) {
            const int m = tile + j;
            const float x = px[m], y = py[m], z = pz[m];
            const int base = 8 * (j >> 1) + (j & 1);
            smf[base + 0] = -2.f * x;
            smf[base + 2] = -2.f * y;
            smf[base + 4] = -2.f * z;
            smf[base + 6] = x * x + y * y + z * z;
        }
        __syncthreads();

#pragma unroll 4
        for (int p = 0; p < PAIRS; p++) {
            const ulonglong2 v0 = sm2[2 * p];       // xx, yy  (LDS.128 broadcast)
            const ulonglong2 v1 = sm2[2 * p + 1];   // zz, ww
#pragma unroll
            for (int u = 0; u < UPT; u++) {
                float lo, hi;
                dot2(axd[u], ayd[u], azd[u], v0.x, v0.y, v1.x, v1.y, lo, hi);
                eml[u] = fminf(eml[u], lo);
                emh[u] = fminf(emh[u], hi);
            }
        }
    }

    // Per-thread sum of dist12 over its n-points.
    float sum = 0.f;
#pragma unroll
    for (int u = 0; u < UPT; u++)
        sum += a2[u] + fminf(eml[u], emh[u]);

    // Deterministic block reduction.
#pragma unroll
    for (int off = 16; off > 0; off >>= 1)
        sum += __shfl_down_sync(0xFFFFFFFFu, sum, off);
    const int wid = t >> 5;
    if ((t & 31) == 0) red[wid] = sum;
    __syncthreads();
    if (t == 0) {
        float s = 0.f;
#pragma unroll
        for (int w = 0; w < THREADS / 32; w++) s += red[w];
        g_partials[blk] = s;
        __threadfence();
        is_last = (atomicAdd(&g_count, 1) == GRID - 1);
    }
    __syncthreads();

    // Last block: fixed-order final reduction (deterministic), reset counter.
    if (is_last && t < GRID) {
        __threadfence();
        float v = g_partials[t];
#pragma unroll
        for (int off = 16; off > 0; off >>= 1)
            v += __shfl_down_sync(0xFFFFFFFFu, v, off);
        if ((t & 31) == 0) red[t >> 5] = v;
    }
    if (is_last) __syncthreads();
    if (is_last && t == 0) {
        float s = red[0] + red[1] + red[2] + red[3];
        out[0] = s * (2.0f / (float)(BATCH * NPTS));
        g_count = 0;   // reset for next graph replay
    }
}

extern "C" void kernel_launch(void* const* d_in, const int* in_sizes, int n_in,
                              void* d_out, int out_size)
{
    (void)in_sizes; (void)n_in; (void)out_size;
    chamfer_sym_kernel<<<GRID, THREADS>>>((const float*)d_in[0], (float*)d_out);
}

// round 9
// speedup vs baseline: 1.3288x; 1.3288x over previous
#include <cuda_runtime.h>
#include <cuda_bf16.h>

// SymmetryLoss: chamfer(mirror(xyz), xyz), yz-plane mirror.
// xyz: (B=16, 3, N=4096) fp32 NCHW -> scalar loss.
//
// d2 symmetric => loss = (2/(B*N)) * sum_n min_m [a2_n + (b2_m - 2 a_n.b_m)]
// f32x2-packed over m (FFMA2), UPT=8 n-points/thread to amortize smem
// broadcast bandwidth (the measured bottleneck), m split 4-ways across
// blocks with exact min-combine. One launch, fused hierarchical reduction.

#define BATCH    16
#define NPTS     4096
#define THREADS  256
#define UPT      8                      // n-points per thread
#define NPB      (THREADS * UPT)        // 2048 n per block
#define NCHUNKS  (BATCH * NPTS / NPB)   // 32 n-chunks
#define MSPLIT   4
#define MCHUNK   (NPTS / MSPLIT)        // 1024 m per block
#define PAIRS    (MCHUNK / 2)           // 512 m-pairs
#define GRID     (NCHUNKS * MSPLIT)     // 128 blocks
#define TOTAL_N  (BATCH * NPTS)         // 65536

__device__ float4 g_part[TOTAL_N];      // per-n partial dist, one float per m-split
__device__ float  g_bsum[NCHUNKS];
__device__ int    g_cnt[NCHUNKS];       // zero-init; each combiner resets its slot
__device__ int    g_count = 0;

// (lo,hi) = ax*xx + ay*yy + az*zz + ww  elementwise on f32x2 lanes.
__device__ __forceinline__ void dot2(
    unsigned long long axd, unsigned long long ayd, unsigned long long azd,
    unsigned long long xx, unsigned long long yy,
    unsigned long long zz, unsigned long long ww,
    float& lo, float& hi)
{
    asm("{\n\t"
        ".reg .b64 t;\n\t"
        "fma.rn.f32x2 t, %4, %7, %8;\n\t"
        "fma.rn.f32x2 t, %3, %6, t;\n\t"
        "fma.rn.f32x2 t, %2, %5, t;\n\t"
        "mov.b64 {%0, %1}, t;\n\t"
        "}"
        : "=f"(lo), "=f"(hi)
        : "l"(axd), "l"(ayd), "l"(azd), "l"(xx), "l"(yy), "l"(zz), "l"(ww));
}

__device__ __forceinline__ unsigned long long dupf(float v)
{
    unsigned long long d;
    asm("mov.b64 %0, {%1, %1};" : "=l"(d) : "f"(v));
    return d;
}

__global__ __launch_bounds__(THREADS, 1)
void chamfer_sym_kernel(const float* __restrict__ xyz, float* __restrict__ out)
{
    // Pair p: sm2[2p]=(xx,yy), sm2[2p+1]=(zz,ww); components are f32x2
    // over (even m, odd m). 16 KB.
    __shared__ ulonglong2 sm2[2 * PAIRS];
    __shared__ float      red[THREADS / 32];
    __shared__ bool       last_nc, last_all;

    const int blk = blockIdx.x;
    const int s   = blk & (MSPLIT - 1);   // m-split
    const int nc  = blk >> 2;             // n-chunk 0..31
    const int b   = nc >> 1;              // batch
    const int t   = threadIdx.x;

    const float* __restrict__ px = xyz + (size_t)b * 3 * NPTS;
    const float* __restrict__ py = px + NPTS;
    const float* __restrict__ pz = px + 2 * NPTS;

    // ---- load mirrored a-points (UPT per thread) ----
    const int nloc0 = (nc & 1) * NPB;     // n offset within batch
    unsigned long long axd[UPT], ayd[UPT], azd[UPT];
    float a2[UPT], eml[UPT], emh[UPT];
#pragma unroll
    for (int u = 0; u < UPT; u++) {
        const int n = nloc0 + u * THREADS + t;
        const float x = px[n], y = py[n], z = pz[n];
        axd[u] = dupf(-x);
        ayd[u] = dupf(y);
        azd[u] = dupf(z);
        a2[u]  = x * x + y * y + z * z;
        eml[u] = 3.4e38f;
        emh[u] = 3.4e38f;
    }

    // ---- fill m-tile (this block's 1024-m slice) ----
    {
        float* smf = (float*)sm2;
        const int mbase = s * MCHUNK;
        for (int j = t; j < MCHUNK; j += THREADS) {
            const int m = mbase + j;
            const float x = px[m], y = py[m], z = pz[m];
            const int base = 8 * (j >> 1) + (j & 1);
            smf[base + 0] = -2.f * x;
            smf[base + 2] = -2.f * y;
            smf[base + 4] = -2.f * z;
            smf[base + 6] = x * x + y * y + z * z;
        }
    }
    __syncthreads();

    // ---- main sweep: 512 m-pairs x 8 n-points ----
#pragma unroll 2
    for (int p = 0; p < PAIRS; p++) {
        const ulonglong2 v0 = sm2[2 * p];       // xx, yy (broadcast LDS.128)
        const ulonglong2 v1 = sm2[2 * p + 1];   // zz, ww
#pragma unroll
        for (int u = 0; u < UPT; u++) {
            float lo, hi;
            dot2(axd[u], ayd[u], azd[u], v0.x, v0.y, v1.x, v1.y, lo, hi);
            eml[u] = fminf(eml[u], lo);
            emh[u] = fminf(emh[u], hi);
        }
    }

    // ---- write per-n partial dist for this m-split ----
#pragma unroll
    for (int u = 0; u < UPT; u++) {
        const int n = nc * NPB + u * THREADS + t;
        ((float*)(g_part + n))[s] = a2[u] + fminf(eml[u], emh[u]);
    }
    __threadfence();
    __syncthreads();

    // ---- per-n-chunk combine: last of the 4 m-split blocks ----
    if (t == 0) last_nc = (atomicAdd(&g_cnt[nc], 1) == MSPLIT - 1);
    __syncthreads();
    if (!last_nc) return;

    __threadfence();
    float sum = 0.f;
    {
        const float4* gp = g_part + nc * NPB;
#pragma unroll
        for (int k = 0; k < NPB / THREADS; k++) {     // 8 rows/thread
            const float4 v = gp[k * THREADS + t];
            sum += fminf(fminf(v.x, v.y), fminf(v.z, v.w));
        }
    }
#pragma unroll
    for (int off = 16; off > 0; off >>= 1)
        sum += __shfl_down_sync(0xFFFFFFFFu, sum, off);
    if ((t & 31) == 0) red[t >> 5] = sum;
    __syncthreads();
    if (t == 0) {
        float sc = 0.f;
#pragma unroll
        for (int w = 0; w < THREADS / 32; w++) sc += red[w];
        g_bsum[nc] = sc;
        g_cnt[nc]  = 0;                    // reset for next replay
        __threadfence();
        last_all = (atomicAdd(&g_count, 1) == NCHUNKS - 1);
    }
    __syncthreads();

    // ---- final: last combiner sums the 32 chunk partials ----
    if (last_all && t == 0) {
        __threadfence();
        float tot = 0.f;
#pragma unroll
        for (int k = 0; k < NCHUNKS; k++) tot += g_bsum[k];
        out[0] = tot * (2.0f / (float)(BATCH * NPTS));
        g_count = 0;                       // reset for next replay
    }
}

extern "C" void kernel_launch(void* const* d_in, const int* in_sizes, int n_in,
                              void* d_out, int out_size)
{
    (void)in_sizes; (void)n_in; (void)out_size;
    chamfer_sym_kernel<<<GRID, THREADS>>>((const float*)d_in[0], (float*)d_out);
}